// round 14
// baseline (speedup 1.0000x reference)
#include <cuda_runtime.h>
#include <cuda_fp16.h>
#include <math.h>
#include <float.h>
#include <stdint.h>

#define BATCH 4
#define SEQ   2048
#define DM    1024
#define ROWS  (BATCH * SEQ)   // 8192

#define BM 128
#define BN 128
#define BK 64                 // halves per K-slice (doubled vs R13)
#define LDH 72                // halves per smem row (144B stride; LDSM conflict-free)
#define THREADS 128
#define STAGES 3
#define MAT_BYTES (128 * LDH * 2)            // 18432 per matrix tile
#define STG_BYTES (2 * MAT_BYTES)            // 36864
#define SMEM_BYTES (STAGES * STG_BYTES)      // 110592 (2 CTAs = 216KB <= 227KB)

// Scratch (allocation-free rule: __device__ globals)
__device__ __half g_xh[(size_t)ROWS * DM];
__device__ __half g_wq[(size_t)DM * DM];
__device__ __half g_wk[(size_t)DM * DM];
__device__ __half g_wv[(size_t)DM * DM];
__device__ __half g_qh[(size_t)ROWS * DM];
__device__ __half g_kh[(size_t)ROWS * DM];
__device__ __half g_vt[(size_t)BATCH * DM * SEQ];  // V transposed per batch
__device__ float  g_s [(size_t)BATCH * SEQ * SEQ]; // fp32 scores
__device__ __half g_p [(size_t)BATCH * SEQ * SEQ]; // fp16 probs

__device__ __forceinline__ void mma16(float c[4], const unsigned a[4], const unsigned b[2]) {
    asm volatile(
        "mma.sync.aligned.m16n8k16.row.col.f32.f16.f16.f32 "
        "{%0,%1,%2,%3},{%4,%5,%6,%7},{%8,%9},{%0,%1,%2,%3};"
        : "+f"(c[0]), "+f"(c[1]), "+f"(c[2]), "+f"(c[3])
        : "r"(a[0]), "r"(a[1]), "r"(a[2]), "r"(a[3]), "r"(b[0]), "r"(b[1]));
}

__device__ __forceinline__ void ldsm_x4(unsigned r[4], unsigned addr) {
    asm volatile("ldmatrix.sync.aligned.m8n8.x4.shared.b16 {%0,%1,%2,%3}, [%4];"
        : "=r"(r[0]), "=r"(r[1]), "=r"(r[2]), "=r"(r[3]) : "r"(addr));
}

__device__ __forceinline__ void cp16(unsigned smem_u32, const void* gptr) {
    asm volatile("cp.async.cg.shared.global [%0], [%1], 16;\n" :: "r"(smem_u32), "l"(gptr));
}
__device__ __forceinline__ void cp_commit() { asm volatile("cp.async.commit_group;\n"); }
template<int N>
__device__ __forceinline__ void cp_wait() { asm volatile("cp.async.wait_group %0;\n" :: "n"(N)); }

// One k16-step of fragment loads (4 A x4 + 4 B x4), ks in [0,4).
__device__ __forceinline__ void load_frags(
    unsigned sA, unsigned sB, unsigned aoff, unsigned boff, int ks,
    unsigned af[4][4], unsigned bf[8][2])
{
    #pragma unroll
    for (int i = 0; i < 4; ++i)
        ldsm_x4(af[i], sA + aoff + (unsigned)((i * 16 * LDH + ks * 16) * 2));
    #pragma unroll
    for (int j2 = 0; j2 < 4; ++j2) {
        unsigned bb[4];
        ldsm_x4(bb, sB + boff + (unsigned)((j2 * 16 * LDH + ks * 16) * 2));
        bf[2 * j2][0] = bb[0]; bf[2 * j2][1] = bb[1];
        bf[2 * j2 + 1][0] = bb[2]; bf[2 * j2 + 1][1] = bb[3];
    }
}

// ---------------------------------------------------------------------------
// Merged fp32 -> fp16 conversion of x, Wq, Wk, Wv (one launch).
// ---------------------------------------------------------------------------
#define NX8 (ROWS * DM / 8)   // 1048576
#define NW8 (DM * DM / 8)     // 131072

__global__ void cvt_all(const float* __restrict__ x,
                        const float* __restrict__ Wq, const float* __restrict__ Wk,
                        const float* __restrict__ Wv,
                        __half* __restrict__ xh, __half* __restrict__ wq,
                        __half* __restrict__ wk, __half* __restrict__ wv)
{
    int i = blockIdx.x * blockDim.x + threadIdx.x;
    const float* in;
    __half* out;
    int j;
    if (i < NX8)                { in = x;  out = xh; j = i; }
    else if (i < NX8 + NW8)     { in = Wq; out = wq; j = i - NX8; }
    else if (i < NX8 + 2 * NW8) { in = Wk; out = wk; j = i - NX8 - NW8; }
    else if (i < NX8 + 3 * NW8) { in = Wv; out = wv; j = i - NX8 - 2 * NW8; }
    else return;

    float4 a = ((const float4*)in)[2 * j];
    float4 b = ((const float4*)in)[2 * j + 1];
    __half2 h0 = __float22half2_rn(make_float2(a.x, a.y));
    __half2 h1 = __float22half2_rn(make_float2(a.z, a.w));
    __half2 h2 = __float22half2_rn(make_float2(b.x, b.y));
    __half2 h3 = __float22half2_rn(make_float2(b.z, b.w));
    uint4 o;
    o.x = *(unsigned*)&h0; o.y = *(unsigned*)&h1;
    o.z = *(unsigned*)&h2; o.w = *(unsigned*)&h3;
    ((uint4*)out)[j] = o;
}

// ---------------------------------------------------------------------------
// Merged QKV projection (BK=64, STAGES=3, single-buffered fragments).
// z=0: q = x Wq^T + bq ; z=1: k = x Wk^T + bk ; z=2: vt = (x Wv^T + bv)^T
// ---------------------------------------------------------------------------
__global__ __launch_bounds__(THREADS, 2) void mm_qkv(
    const __half* __restrict__ A,
    const __half* __restrict__ Wq, const __half* __restrict__ Wk, const __half* __restrict__ Wv,
    const float* __restrict__ bqp, const float* __restrict__ bkp, const float* __restrict__ bvp,
    __half* __restrict__ Oq, __half* __restrict__ Ok, __half* __restrict__ Ovt)
{
    const int z = blockIdx.z;
    const __half* B = (z == 0) ? Wq : (z == 1) ? Wk : Wv;
    const float* bias = (z == 0) ? bqp : (z == 1) ? bkp : bvp;

    const int row0 = blockIdx.y * BM;
    const int col0 = blockIdx.x * BN;
    const int nIter = DM / BK;   // 16

    extern __shared__ __align__(16) __half smem_h[];
    const unsigned smem_base = (unsigned)__cvta_generic_to_shared(smem_h);

    const int tid = threadIdx.x;
    // 128 rows x 8 chunks (16B) per tile = 1024 chunks, 8 per thread.
    auto issue = [&](int it) {
        const int k0 = it * BK;
        const unsigned sa = smem_base + (it % STAGES) * STG_BYTES;
        const unsigned sb = sa + MAT_BYTES;
        #pragma unroll
        for (int t = 0; t < 8; ++t) {
            int cid = tid + t * THREADS;
            int r = cid >> 3, c8 = (cid & 7) * 8;
            cp16(sa + (r * LDH + c8) * 2, A + (size_t)(row0 + r) * DM + k0 + c8);
        }
        #pragma unroll
        for (int t = 0; t < 8; ++t) {
            int cid = tid + t * THREADS;
            int r = cid >> 3, c8 = (cid & 7) * 8;
            cp16(sb + (r * LDH + c8) * 2, B + (size_t)(col0 + r) * DM + k0 + c8);
        }
    };

    const int lane = tid & 31;
    const int wid = tid >> 5;
    const int wm = (wid >> 1) * 64;
    const int wn = (wid & 1) * 64;
    const int lq = lane >> 2, lr = lane & 3;

    const int lr8 = lane & 7;
    const unsigned aoff = (unsigned)(((wm + lr8 + ((lane >> 3) & 1) * 8) * LDH
                                      + ((lane >> 4) & 1) * 8) * 2);
    const unsigned boff = (unsigned)(((wn + lr8 + ((lane >> 4) & 1) * 8) * LDH
                                      + ((lane >> 3) & 1) * 8) * 2);

    float acc[4][8][4] = {};
    unsigned af[4][4], bf[8][2];

    issue(0); cp_commit();
    issue(1); cp_commit();

    for (int it = 0; it < nIter; ++it) {
        cp_wait<1>();
        __syncthreads();

        if (it + 2 < nIter) issue(it + 2);
        cp_commit();

        const unsigned sA = smem_base + (it % STAGES) * STG_BYTES;
        const unsigned sB = sA + MAT_BYTES;

        #pragma unroll
        for (int ks = 0; ks < 4; ++ks) {             // four k16 steps per BK=64
            load_frags(sA, sB, aoff, boff, ks, af, bf);
            #pragma unroll
            for (int i = 0; i < 4; ++i)
                #pragma unroll
                for (int j = 0; j < 8; ++j)
                    mma16(acc[i][j], af[i], bf[j]);
        }
    }
    __syncthreads();

    if (z < 2) {
        __half* C = (z == 0) ? Oq : Ok;
        #pragma unroll
        for (int i = 0; i < 4; ++i) {
            const int r = row0 + wm + i * 16 + lq;
            #pragma unroll
            for (int j = 0; j < 8; ++j) {
                const int c = col0 + wn + j * 8 + 2 * lr;
                const float b0 = bias[c], b1 = bias[c + 1];
                *(__half2*)&C[(size_t)r * DM + c] =
                    __float22half2_rn(make_float2(acc[i][j][0] + b0, acc[i][j][1] + b1));
                *(__half2*)&C[(size_t)(r + 8) * DM + c] =
                    __float22half2_rn(make_float2(acc[i][j][2] + b0, acc[i][j][3] + b1));
            }
        }
    } else {
        // transposed store via per-warp smem staging (64n x 64m, pad 72)
        __half* ts = smem_h + (size_t)wid * 64 * 72;
        #pragma unroll
        for (int i = 0; i < 4; ++i) {
            const int ml = i * 16 + lq;
            #pragma unroll
            for (int j = 0; j < 8; ++j) {
                const int nl = j * 8 + 2 * lr;
                const int c = col0 + wn + nl;
                const float b0 = bias[c], b1 = bias[c + 1];
                ts[nl * 72 + ml]           = __float2half_rn(acc[i][j][0] + b0);
                ts[(nl + 1) * 72 + ml]     = __float2half_rn(acc[i][j][1] + b1);
                ts[nl * 72 + ml + 8]       = __float2half_rn(acc[i][j][2] + b0);
                ts[(nl + 1) * 72 + ml + 8] = __float2half_rn(acc[i][j][3] + b1);
            }
        }
        __syncwarp();
        __half* vtb = Ovt + (size_t)(row0 >> 11) * DM * SEQ;
        const int s0 = (row0 & (SEQ - 1)) + wm;
        #pragma unroll
        for (int nr2 = 0; nr2 < 2; ++nr2) {
            const int nr = lane + nr2 * 32;
            const int n = col0 + wn + nr;
            #pragma unroll
            for (int i8 = 0; i8 < 8; ++i8) {
                uint4 v = *(uint4*)&ts[nr * 72 + i8 * 8];
                *(uint4*)&vtb[(size_t)n * SEQ + s0 + i8 * 8] = v;
            }
        }
    }
}

// ---------------------------------------------------------------------------
// fp16 m16n8k16 GEMM (BK=64, STAGES=3, single-buffered fragments).
// MODE 1: S[b] = (Q K^T)/32   fp32 out; packed triangular grid.
// MODE 2: O[b] = P Vt^T       fp32 out, causal K-limit, longest-first order.
// ---------------------------------------------------------------------------
template<int MODE>
__global__ __launch_bounds__(THREADS, 2) void mm_h(
    const __half* __restrict__ Ag, const __half* __restrict__ Bg,
    void* __restrict__ Cg)
{
    int row0, col0, bz;
    if (MODE == 1) {
        const int t = blockIdx.x;
        int y = (int)((sqrtf(8.0f * (float)t + 1.0f) - 1.0f) * 0.5f);
        while ((y + 1) * (y + 2) / 2 <= t) ++y;
        while (y * (y + 1) / 2 > t) --y;
        const int xcol = t - y * (y + 1) / 2;
        row0 = y * BM; col0 = xcol * BN;
        bz = blockIdx.y;
    } else {
        const int by = (int)gridDim.y - 1 - (int)blockIdx.y;  // longest first
        row0 = by * BM;
        col0 = blockIdx.x * BN;
        bz = blockIdx.z;
    }

    const __half* A = Ag;
    const __half* B = Bg;
    int ldA = DM, ldB = DM;
    if (MODE == 1) {
        size_t off = (size_t)bz * SEQ * DM;
        A += off; B += off;
    }
    if (MODE == 2) {
        A += (size_t)bz * SEQ * SEQ;
        B += (size_t)bz * DM * SEQ;
        ldA = SEQ; ldB = SEQ;
    }
    const int kEnd  = (MODE == 2) ? (row0 + BM) : DM;
    const int nIter = kEnd / BK;    // >= 2 always (PV min: 128/64)

    extern __shared__ __align__(16) __half smem_h[];
    const unsigned smem_base = (unsigned)__cvta_generic_to_shared(smem_h);

    const int tid = threadIdx.x;
    auto issue = [&](int it) {
        const int k0 = it * BK;
        const unsigned sa = smem_base + (it % STAGES) * STG_BYTES;
        const unsigned sb = sa + MAT_BYTES;
        #pragma unroll
        for (int t = 0; t < 8; ++t) {
            int cid = tid + t * THREADS;
            int r = cid >> 3, c8 = (cid & 7) * 8;
            cp16(sa + (r * LDH + c8) * 2, A + (size_t)(row0 + r) * ldA + k0 + c8);
        }
        #pragma unroll
        for (int t = 0; t < 8; ++t) {
            int cid = tid + t * THREADS;
            int r = cid >> 3, c8 = (cid & 7) * 8;
            cp16(sb + (r * LDH + c8) * 2, B + (size_t)(col0 + r) * ldB + k0 + c8);
        }
    };

    const int lane = tid & 31;
    const int wid = tid >> 5;
    const int wm = (wid >> 1) * 64;
    const int wn = (wid & 1) * 64;
    const int lq = lane >> 2, lr = lane & 3;

    const int lr8 = lane & 7;
    const unsigned aoff = (unsigned)(((wm + lr8 + ((lane >> 3) & 1) * 8) * LDH
                                      + ((lane >> 4) & 1) * 8) * 2);
    const unsigned boff = (unsigned)(((wn + lr8 + ((lane >> 4) & 1) * 8) * LDH
                                      + ((lane >> 3) & 1) * 8) * 2);

    float acc[4][8][4] = {};
    unsigned af[4][4], bf[8][2];

    issue(0); cp_commit();
    issue(1); cp_commit();

    for (int it = 0; it < nIter; ++it) {
        cp_wait<1>();
        __syncthreads();

        if (it + 2 < nIter) issue(it + 2);
        cp_commit();

        const unsigned sA = smem_base + (it % STAGES) * STG_BYTES;
        const unsigned sB = sA + MAT_BYTES;

        #pragma unroll
        for (int ks = 0; ks < 4; ++ks) {
            load_frags(sA, sB, aoff, boff, ks, af, bf);
            #pragma unroll
            for (int i = 0; i < 4; ++i)
                #pragma unroll
                for (int j = 0; j < 8; ++j)
                    mma16(acc[i][j], af[i], bf[j]);
        }
    }

    if (MODE == 1) {
        float* C = (float*)Cg + (size_t)bz * SEQ * SEQ;
        const float scale = 1.0f / 32.0f;
        #pragma unroll
        for (int i = 0; i < 4; ++i) {
            const int r = row0 + wm + i * 16 + lq;
            #pragma unroll
            for (int j = 0; j < 8; ++j) {
                const int c = col0 + wn + j * 8 + 2 * lr;
                *(float2*)&C[(size_t)r * SEQ + c] =
                    make_float2(acc[i][j][0] * scale, acc[i][j][1] * scale);
                *(float2*)&C[(size_t)(r + 8) * SEQ + c] =
                    make_float2(acc[i][j][2] * scale, acc[i][j][3] * scale);
            }
        }
    } else {
        float* C = (float*)Cg + (size_t)bz * SEQ * DM;
        #pragma unroll
        for (int i = 0; i < 4; ++i) {
            const int r = row0 + wm + i * 16 + lq;
            #pragma unroll
            for (int j = 0; j < 8; ++j) {
                const int c = col0 + wn + j * 8 + 2 * lr;
                *(float2*)&C[(size_t)r * DM + c] = make_float2(acc[i][j][0], acc[i][j][1]);
                *(float2*)&C[(size_t)(r + 8) * DM + c] = make_float2(acc[i][j][2], acc[i][j][3]);
            }
        }
    }
}

// ---------------------------------------------------------------------------
// Registerized softmax (R12-proven): row in registers, one read, one exp,
// one fp16 write.
// ---------------------------------------------------------------------------
__global__ __launch_bounds__(256) void softmax_kernel(
    const float* __restrict__ S, __half* __restrict__ P)
{
    __shared__ float redm[8], reds[8];
    const int r = blockIdx.x;
    const int qi = r & (SEQ - 1);
    const float* row = S + (size_t)r * SEQ;
    __half* prow = P + (size_t)r * SEQ;
    const int L = qi + 1;
    const int L4 = L >> 2;
    const int tid = threadIdx.x;
    const int wid = tid >> 5, lane = tid & 31;

    const bool h0 = tid < L4;
    const bool h1 = tid + 256 < L4;
    const int ti = L4 * 4 + tid;
    const bool ht = ti < L;
    float4 v0, v1;
    float vt = 0.0f;
    if (h0) v0 = ((const float4*)row)[tid];
    if (h1) v1 = ((const float4*)row)[tid + 256];
    if (ht) vt = row[ti];

    float m = -FLT_MAX;
    if (h0) m = fmaxf(fmaxf(v0.x, v0.y), fmaxf(v0.z, v0.w));
    if (h1) m = fmaxf(m, fmaxf(fmaxf(v1.x, v1.y), fmaxf(v1.z, v1.w)));
    if (ht) m = fmaxf(m, vt);
    #pragma unroll
    for (int o = 16; o; o >>= 1) m = fmaxf(m, __shfl_xor_sync(0xffffffffu, m, o));
    if (lane == 0) redm[wid] = m;
    __syncthreads();
    float M = -FLT_MAX;
    #pragma unroll
    for (int w = 0; w < 8; ++w) M = fmaxf(M, redm[w]);

    const float c2 = 1.4426950408889634f;
    float s = 0.0f;
    float4 e0, e1;
    float et = 0.0f;
    if (h0) {
        e0.x = exp2f((v0.x - M) * c2); e0.y = exp2f((v0.y - M) * c2);
        e0.z = exp2f((v0.z - M) * c2); e0.w = exp2f((v0.w - M) * c2);
        s += e0.x + e0.y + e0.z + e0.w;
    }
    if (h1) {
        e1.x = exp2f((v1.x - M) * c2); e1.y = exp2f((v1.y - M) * c2);
        e1.z = exp2f((v1.z - M) * c2); e1.w = exp2f((v1.w - M) * c2);
        s += e1.x + e1.y + e1.z + e1.w;
    }
    if (ht) {
        et = exp2f((vt - M) * c2);
        s += et;
    }
    #pragma unroll
    for (int o = 16; o; o >>= 1) s += __shfl_xor_sync(0xffffffffu, s, o);
    if (lane == 0) reds[wid] = s;
    __syncthreads();
    float Stot = 0.0f;
    #pragma unroll
    for (int w = 0; w < 8; ++w) Stot += reds[w];
    const float inv = 1.0f / Stot;

    if (h0) {
        __half2 a = __float22half2_rn(make_float2(e0.x * inv, e0.y * inv));
        __half2 b = __float22half2_rn(make_float2(e0.z * inv, e0.w * inv));
        uint2 o; o.x = *(unsigned*)&a; o.y = *(unsigned*)&b;
        ((uint2*)prow)[tid] = o;
    }
    if (h1) {
        __half2 a = __float22half2_rn(make_float2(e1.x * inv, e1.y * inv));
        __half2 b = __float22half2_rn(make_float2(e1.z * inv, e1.w * inv));
        uint2 o; o.x = *(unsigned*)&a; o.y = *(unsigned*)&b;
        ((uint2*)prow)[tid + 256] = o;
    }
    if (ht) prow[ti] = __float2half_rn(et * inv);

    const int zEnd = (qi & ~127) + 128;
    for (int j = L + tid; j < zEnd; j += 256) prow[j] = __float2half_rn(0.0f);
}

// ---------------------------------------------------------------------------
extern "C" void kernel_launch(void* const* d_in, const int* in_sizes, int n_in,
                              void* d_out, int out_size)
{
    (void)in_sizes; (void)n_in; (void)out_size;
    const float* x  = (const float*)d_in[0];
    const float* Wq = (const float*)d_in[1];
    const float* bq = (const float*)d_in[2];
    const float* Wk = (const float*)d_in[3];
    const float* bk = (const float*)d_in[4];
    const float* Wv = (const float*)d_in[5];
    const float* bv = (const float*)d_in[6];
    float* out = (float*)d_out;

    __half *xh, *wq, *wk, *wv, *qh, *kh, *vt, *p;
    float *s;
    cudaGetSymbolAddress((void**)&xh, g_xh);
    cudaGetSymbolAddress((void**)&wq, g_wq);
    cudaGetSymbolAddress((void**)&wk, g_wk);
    cudaGetSymbolAddress((void**)&wv, g_wv);
    cudaGetSymbolAddress((void**)&qh, g_qh);
    cudaGetSymbolAddress((void**)&kh, g_kh);
    cudaGetSymbolAddress((void**)&vt, g_vt);
    cudaGetSymbolAddress((void**)&p,  g_p);
    cudaGetSymbolAddress((void**)&s,  g_s);

    cudaFuncSetAttribute(mm_qkv,  cudaFuncAttributeMaxDynamicSharedMemorySize, SMEM_BYTES);
    cudaFuncSetAttribute(mm_h<1>, cudaFuncAttributeMaxDynamicSharedMemorySize, SMEM_BYTES);
    cudaFuncSetAttribute(mm_h<2>, cudaFuncAttributeMaxDynamicSharedMemorySize, SMEM_BYTES);

    dim3 blk(THREADS);

    // Merged operand conversion (x + 3 weight matrices), one launch.
    const int nAll = NX8 + 3 * NW8;
    cvt_all<<<(nAll + 255) / 256, 256>>>(x, Wq, Wk, Wv, xh, wq, wk, wv);

    // Merged QKV projections (V written transposed): (8, 64, 3) = 1536 CTAs
    dim3 gProj(DM / BN, ROWS / BM, 3);
    mm_qkv<<<gProj, blk, SMEM_BYTES>>>(xh, wq, wk, wv, bq, bk, bv, qh, kh, vt);

    // Causal scores (fp32 out): packed triangular grid, 136 live tiles x 4
    const int nTiles = (SEQ / BM) * (SEQ / BM + 1) / 2;   // 136
    dim3 gScores(nTiles, BATCH);
    mm_h<1><<<gScores, blk, SMEM_BYTES>>>(qh, kh, s);

    // Registerized row softmax (fp32 -> fp16 probs)
    softmax_kernel<<<ROWS, 256>>>(s, p);

    // O = P Vt^T (fp32 out), longest CTAs first
    dim3 gPV(DM / BN, SEQ / BM, BATCH);          // (8, 16, 4)
    mm_h<2><<<gPV, blk, SMEM_BYTES>>>(p, vt, out);
}

// round 15
// speedup vs baseline: 1.0045x; 1.0045x over previous
#include <cuda_runtime.h>
#include <cuda_fp16.h>
#include <math.h>
#include <float.h>
#include <stdint.h>

#define BATCH 4
#define SEQ   2048
#define DM    1024
#define ROWS  (BATCH * SEQ)   // 8192

#define BM 128
#define BN 128
#define BK 32                 // halves per K-slice (R12-proven)
#define LDH 40                // halves per smem row (80B; LDSM conflict-free)
#define THREADS 128
#define STAGES 4
#define MAT_BYTES (128 * LDH * 2)            // 10240 per matrix tile
#define STG_BYTES (2 * MAT_BYTES)            // 20480
#define SMEM_BYTES (STAGES * STG_BYTES)      // 81920

// Scratch (allocation-free rule: __device__ globals)
__device__ __half g_xh[(size_t)ROWS * DM];
__device__ __half g_wq[(size_t)DM * DM];
__device__ __half g_wk[(size_t)DM * DM];
__device__ __half g_wv[(size_t)DM * DM];
__device__ __half g_qh[(size_t)ROWS * DM];
__device__ __half g_kh[(size_t)ROWS * DM];
__device__ __half g_vt[(size_t)BATCH * DM * SEQ];  // V transposed per batch
__device__ float  g_s [(size_t)BATCH * SEQ * SEQ]; // fp32 scores
__device__ __half g_p [(size_t)BATCH * SEQ * SEQ]; // fp16 probs

__device__ __forceinline__ void mma16(float c[4], const unsigned a[4], const unsigned b[2]) {
    asm volatile(
        "mma.sync.aligned.m16n8k16.row.col.f32.f16.f16.f32 "
        "{%0,%1,%2,%3},{%4,%5,%6,%7},{%8,%9},{%0,%1,%2,%3};"
        : "+f"(c[0]), "+f"(c[1]), "+f"(c[2]), "+f"(c[3])
        : "r"(a[0]), "r"(a[1]), "r"(a[2]), "r"(a[3]), "r"(b[0]), "r"(b[1]));
}

__device__ __forceinline__ void ldsm_x4(unsigned r[4], unsigned addr) {
    asm volatile("ldmatrix.sync.aligned.m8n8.x4.shared.b16 {%0,%1,%2,%3}, [%4];"
        : "=r"(r[0]), "=r"(r[1]), "=r"(r[2]), "=r"(r[3]) : "r"(addr));
}

__device__ __forceinline__ void cp16(unsigned smem_u32, const void* gptr) {
    asm volatile("cp.async.cg.shared.global [%0], [%1], 16;\n" :: "r"(smem_u32), "l"(gptr));
}
__device__ __forceinline__ void cp_commit() { asm volatile("cp.async.commit_group;\n"); }
template<int N>
__device__ __forceinline__ void cp_wait() { asm volatile("cp.async.wait_group %0;\n" :: "n"(N)); }

// ---------------------------------------------------------------------------
// Merged fp32 -> fp16 conversion of x, Wq, Wk, Wv (one launch).
// ---------------------------------------------------------------------------
#define NX8 (ROWS * DM / 8)   // 1048576
#define NW8 (DM * DM / 8)     // 131072

__global__ void cvt_all(const float* __restrict__ x,
                        const float* __restrict__ Wq, const float* __restrict__ Wk,
                        const float* __restrict__ Wv,
                        __half* __restrict__ xh, __half* __restrict__ wq,
                        __half* __restrict__ wk, __half* __restrict__ wv)
{
    int i = blockIdx.x * blockDim.x + threadIdx.x;
    const float* in;
    __half* out;
    int j;
    if (i < NX8)                { in = x;  out = xh; j = i; }
    else if (i < NX8 + NW8)     { in = Wq; out = wq; j = i - NX8; }
    else if (i < NX8 + 2 * NW8) { in = Wk; out = wk; j = i - NX8 - NW8; }
    else if (i < NX8 + 3 * NW8) { in = Wv; out = wv; j = i - NX8 - 2 * NW8; }
    else return;

    float4 a = ((const float4*)in)[2 * j];
    float4 b = ((const float4*)in)[2 * j + 1];
    __half2 h0 = __float22half2_rn(make_float2(a.x, a.y));
    __half2 h1 = __float22half2_rn(make_float2(a.z, a.w));
    __half2 h2 = __float22half2_rn(make_float2(b.x, b.y));
    __half2 h3 = __float22half2_rn(make_float2(b.z, b.w));
    uint4 o;
    o.x = *(unsigned*)&h0; o.y = *(unsigned*)&h1;
    o.z = *(unsigned*)&h2; o.w = *(unsigned*)&h3;
    ((uint4*)out)[j] = o;
}

// ---------------------------------------------------------------------------
// QKV projection (R12-proven mainloop). z = blockIdx.z + zbase:
// z=0: q = x Wq^T + bq ; z=1: k = x Wk^T + bk ; z=2: vt = (x Wv^T + bv)^T
// zbase lets the V projection run as its own launch on a forked stream.
// ---------------------------------------------------------------------------
__global__ __launch_bounds__(THREADS, 2) void mm_qkv(
    const __half* __restrict__ A,
    const __half* __restrict__ Wq, const __half* __restrict__ Wk, const __half* __restrict__ Wv,
    const float* __restrict__ bqp, const float* __restrict__ bkp, const float* __restrict__ bvp,
    __half* __restrict__ Oq, __half* __restrict__ Ok, __half* __restrict__ Ovt,
    int zbase)
{
    const int z = blockIdx.z + zbase;
    const __half* B = (z == 0) ? Wq : (z == 1) ? Wk : Wv;
    const float* bias = (z == 0) ? bqp : (z == 1) ? bkp : bvp;

    const int row0 = blockIdx.y * BM;
    const int col0 = blockIdx.x * BN;
    const int nIter = DM / BK;

    extern __shared__ __align__(16) __half smem_h[];
    const unsigned smem_base = (unsigned)__cvta_generic_to_shared(smem_h);

    const int tid = threadIdx.x;
    auto issue = [&](int it) {
        const int k0 = it * BK;
        const unsigned sa = smem_base + (it % STAGES) * STG_BYTES;
        const unsigned sb = sa + MAT_BYTES;
        #pragma unroll
        for (int t = 0; t < 4; ++t) {
            int cid = tid + t * THREADS;
            int r = cid >> 2, c8 = (cid & 3) * 8;
            cp16(sa + (r * LDH + c8) * 2, A + (size_t)(row0 + r) * DM + k0 + c8);
        }
        #pragma unroll
        for (int t = 0; t < 4; ++t) {
            int cid = tid + t * THREADS;
            int r = cid >> 2, c8 = (cid & 3) * 8;
            cp16(sb + (r * LDH + c8) * 2, B + (size_t)(col0 + r) * DM + k0 + c8);
        }
    };

    const int lane = tid & 31;
    const int wid = tid >> 5;
    const int wm = (wid >> 1) * 64;
    const int wn = (wid & 1) * 64;
    const int lq = lane >> 2, lr = lane & 3;

    const int lr8 = lane & 7;
    const unsigned aoff = (unsigned)(((wm + lr8 + ((lane >> 3) & 1) * 8) * LDH
                                      + ((lane >> 4) & 1) * 8) * 2);
    const unsigned boff = (unsigned)(((wn + lr8 + ((lane >> 4) & 1) * 8) * LDH
                                      + ((lane >> 3) & 1) * 8) * 2);

    float acc[4][8][4] = {};

    #pragma unroll
    for (int s = 0; s < STAGES - 1; ++s) {
        issue(s);
        cp_commit();
    }

    for (int it = 0; it < nIter; ++it) {
        cp_wait<STAGES - 2>();
        __syncthreads();

        if (it + STAGES - 1 < nIter) issue(it + STAGES - 1);
        cp_commit();

        const unsigned sA = smem_base + (it % STAGES) * STG_BYTES;
        const unsigned sB = sA + MAT_BYTES;

        #pragma unroll
        for (int ks = 0; ks < 2; ++ks) {
            unsigned af[4][4], bf[8][2];
            #pragma unroll
            for (int i = 0; i < 4; ++i)
                ldsm_x4(af[i], sA + aoff + (unsigned)((i * 16 * LDH + ks * 16) * 2));
            #pragma unroll
            for (int j2 = 0; j2 < 4; ++j2) {
                unsigned bb[4];
                ldsm_x4(bb, sB + boff + (unsigned)((j2 * 16 * LDH + ks * 16) * 2));
                bf[2 * j2][0] = bb[0]; bf[2 * j2][1] = bb[1];
                bf[2 * j2 + 1][0] = bb[2]; bf[2 * j2 + 1][1] = bb[3];
            }
            #pragma unroll
            for (int i = 0; i < 4; ++i)
                #pragma unroll
                for (int j = 0; j < 8; ++j)
                    mma16(acc[i][j], af[i], bf[j]);
        }
    }
    __syncthreads();

    if (z < 2) {
        __half* C = (z == 0) ? Oq : Ok;
        #pragma unroll
        for (int i = 0; i < 4; ++i) {
            const int r = row0 + wm + i * 16 + lq;
            #pragma unroll
            for (int j = 0; j < 8; ++j) {
                const int c = col0 + wn + j * 8 + 2 * lr;
                const float b0 = bias[c], b1 = bias[c + 1];
                *(__half2*)&C[(size_t)r * DM + c] =
                    __float22half2_rn(make_float2(acc[i][j][0] + b0, acc[i][j][1] + b1));
                *(__half2*)&C[(size_t)(r + 8) * DM + c] =
                    __float22half2_rn(make_float2(acc[i][j][2] + b0, acc[i][j][3] + b1));
            }
        }
    } else {
        // transposed store via per-warp smem staging (64n x 64m, pad 72)
        __half* ts = smem_h + (size_t)wid * 64 * 72;
        #pragma unroll
        for (int i = 0; i < 4; ++i) {
            const int ml = i * 16 + lq;
            #pragma unroll
            for (int j = 0; j < 8; ++j) {
                const int nl = j * 8 + 2 * lr;
                const int c = col0 + wn + nl;
                const float b0 = bias[c], b1 = bias[c + 1];
                ts[nl * 72 + ml]           = __float2half_rn(acc[i][j][0] + b0);
                ts[(nl + 1) * 72 + ml]     = __float2half_rn(acc[i][j][1] + b1);
                ts[nl * 72 + ml + 8]       = __float2half_rn(acc[i][j][2] + b0);
                ts[(nl + 1) * 72 + ml + 8] = __float2half_rn(acc[i][j][3] + b1);
            }
        }
        __syncwarp();
        __half* vtb = Ovt + (size_t)(row0 >> 11) * DM * SEQ;
        const int s0 = (row0 & (SEQ - 1)) + wm;
        #pragma unroll
        for (int nr2 = 0; nr2 < 2; ++nr2) {
            const int nr = lane + nr2 * 32;
            const int n = col0 + wn + nr;
            #pragma unroll
            for (int i8 = 0; i8 < 8; ++i8) {
                uint4 v = *(uint4*)&ts[nr * 72 + i8 * 8];
                *(uint4*)&vtb[(size_t)n * SEQ + s0 + i8 * 8] = v;
            }
        }
    }
}

// ---------------------------------------------------------------------------
// fp16 m16n8k16 GEMM (R12-proven).
// MODE 1: S[b] = (Q K^T)/32    fp32 out, skip above-diag tiles
// MODE 2: O[b] = P Vt^T        fp32 out, causal K-limit, longest-first order
// ---------------------------------------------------------------------------
template<int MODE>
__global__ __launch_bounds__(THREADS, 2) void mm_h(
    const __half* __restrict__ Ag, const __half* __restrict__ Bg,
    void* __restrict__ Cg)
{
    const int by = (MODE == 2) ? ((int)gridDim.y - 1 - (int)blockIdx.y) : (int)blockIdx.y;
    const int row0 = by * BM;
    const int col0 = blockIdx.x * BN;
    const __half* A = Ag;
    const __half* B = Bg;
    int ldA = DM, ldB = DM;
    if (MODE == 1) {
        if (col0 > row0) return;
        size_t off = (size_t)blockIdx.z * SEQ * DM;
        A += off; B += off;
    }
    if (MODE == 2) {
        A += (size_t)blockIdx.z * SEQ * SEQ;
        B += (size_t)blockIdx.z * DM * SEQ;
        ldA = SEQ; ldB = SEQ;
    }
    const int kEnd  = (MODE == 2) ? (row0 + BM) : DM;
    const int nIter = kEnd / BK;

    extern __shared__ __align__(16) __half smem_h[];
    const unsigned smem_base = (unsigned)__cvta_generic_to_shared(smem_h);

    const int tid = threadIdx.x;
    auto issue = [&](int it) {
        const int k0 = it * BK;
        const unsigned sa = smem_base + (it % STAGES) * STG_BYTES;
        const unsigned sb = sa + MAT_BYTES;
        #pragma unroll
        for (int t = 0; t < 4; ++t) {
            int cid = tid + t * THREADS;
            int r = cid >> 2, c8 = (cid & 3) * 8;
            cp16(sa + (r * LDH + c8) * 2, A + (size_t)(row0 + r) * ldA + k0 + c8);
        }
        #pragma unroll
        for (int t = 0; t < 4; ++t) {
            int cid = tid + t * THREADS;
            int r = cid >> 2, c8 = (cid & 3) * 8;
            cp16(sb + (r * LDH + c8) * 2, B + (size_t)(col0 + r) * ldB + k0 + c8);
        }
    };

    const int lane = tid & 31;
    const int wid = tid >> 5;
    const int wm = (wid >> 1) * 64;
    const int wn = (wid & 1) * 64;
    const int lq = lane >> 2, lr = lane & 3;

    const int lr8 = lane & 7;
    const unsigned aoff = (unsigned)(((wm + lr8 + ((lane >> 3) & 1) * 8) * LDH
                                      + ((lane >> 4) & 1) * 8) * 2);
    const unsigned boff = (unsigned)(((wn + lr8 + ((lane >> 4) & 1) * 8) * LDH
                                      + ((lane >> 3) & 1) * 8) * 2);

    float acc[4][8][4] = {};

    #pragma unroll
    for (int s = 0; s < STAGES - 1; ++s) {
        if (s < nIter) issue(s);
        cp_commit();
    }

    for (int it = 0; it < nIter; ++it) {
        cp_wait<STAGES - 2>();
        __syncthreads();

        if (it + STAGES - 1 < nIter) issue(it + STAGES - 1);
        cp_commit();

        const unsigned sA = smem_base + (it % STAGES) * STG_BYTES;
        const unsigned sB = sA + MAT_BYTES;

        #pragma unroll
        for (int ks = 0; ks < 2; ++ks) {
            unsigned af[4][4], bf[8][2];
            #pragma unroll
            for (int i = 0; i < 4; ++i)
                ldsm_x4(af[i], sA + aoff + (unsigned)((i * 16 * LDH + ks * 16) * 2));
            #pragma unroll
            for (int j2 = 0; j2 < 4; ++j2) {
                unsigned bb[4];
                ldsm_x4(bb, sB + boff + (unsigned)((j2 * 16 * LDH + ks * 16) * 2));
                bf[2 * j2][0] = bb[0]; bf[2 * j2][1] = bb[1];
                bf[2 * j2 + 1][0] = bb[2]; bf[2 * j2 + 1][1] = bb[3];
            }
            #pragma unroll
            for (int i = 0; i < 4; ++i)
                #pragma unroll
                for (int j = 0; j < 8; ++j)
                    mma16(acc[i][j], af[i], bf[j]);
        }
    }

    if (MODE == 1) {
        float* C = (float*)Cg + (size_t)blockIdx.z * SEQ * SEQ;
        const float scale = 1.0f / 32.0f;
        #pragma unroll
        for (int i = 0; i < 4; ++i) {
            const int r = row0 + wm + i * 16 + lq;
            #pragma unroll
            for (int j = 0; j < 8; ++j) {
                const int c = col0 + wn + j * 8 + 2 * lr;
                *(float2*)&C[(size_t)r * SEQ + c] =
                    make_float2(acc[i][j][0] * scale, acc[i][j][1] * scale);
                *(float2*)&C[(size_t)(r + 8) * SEQ + c] =
                    make_float2(acc[i][j][2] * scale, acc[i][j][3] * scale);
            }
        }
    } else {
        float* C = (float*)Cg + (size_t)blockIdx.z * SEQ * DM;
        #pragma unroll
        for (int i = 0; i < 4; ++i) {
            const int r = row0 + wm + i * 16 + lq;
            #pragma unroll
            for (int j = 0; j < 8; ++j) {
                const int c = col0 + wn + j * 8 + 2 * lr;
                *(float2*)&C[(size_t)r * DM + c] = make_float2(acc[i][j][0], acc[i][j][1]);
                *(float2*)&C[(size_t)(r + 8) * DM + c] = make_float2(acc[i][j][2], acc[i][j][3]);
            }
        }
    }
}

// ---------------------------------------------------------------------------
// Registerized softmax (R12-proven).
// ---------------------------------------------------------------------------
__global__ __launch_bounds__(256) void softmax_kernel(
    const float* __restrict__ S, __half* __restrict__ P)
{
    __shared__ float redm[8], reds[8];
    const int r = blockIdx.x;
    const int qi = r & (SEQ - 1);
    const float* row = S + (size_t)r * SEQ;
    __half* prow = P + (size_t)r * SEQ;
    const int L = qi + 1;
    const int L4 = L >> 2;
    const int tid = threadIdx.x;
    const int wid = tid >> 5, lane = tid & 31;

    const bool h0 = tid < L4;
    const bool h1 = tid + 256 < L4;
    const int ti = L4 * 4 + tid;
    const bool ht = ti < L;
    float4 v0, v1;
    float vt = 0.0f;
    if (h0) v0 = ((const float4*)row)[tid];
    if (h1) v1 = ((const float4*)row)[tid + 256];
    if (ht) vt = row[ti];

    float m = -FLT_MAX;
    if (h0) m = fmaxf(fmaxf(v0.x, v0.y), fmaxf(v0.z, v0.w));
    if (h1) m = fmaxf(m, fmaxf(fmaxf(v1.x, v1.y), fmaxf(v1.z, v1.w)));
    if (ht) m = fmaxf(m, vt);
    #pragma unroll
    for (int o = 16; o; o >>= 1) m = fmaxf(m, __shfl_xor_sync(0xffffffffu, m, o));
    if (lane == 0) redm[wid] = m;
    __syncthreads();
    float M = -FLT_MAX;
    #pragma unroll
    for (int w = 0; w < 8; ++w) M = fmaxf(M, redm[w]);

    const float c2 = 1.4426950408889634f;
    float s = 0.0f;
    float4 e0, e1;
    float et = 0.0f;
    if (h0) {
        e0.x = exp2f((v0.x - M) * c2); e0.y = exp2f((v0.y - M) * c2);
        e0.z = exp2f((v0.z - M) * c2); e0.w = exp2f((v0.w - M) * c2);
        s += e0.x + e0.y + e0.z + e0.w;
    }
    if (h1) {
        e1.x = exp2f((v1.x - M) * c2); e1.y = exp2f((v1.y - M) * c2);
        e1.z = exp2f((v1.z - M) * c2); e1.w = exp2f((v1.w - M) * c2);
        s += e1.x + e1.y + e1.z + e1.w;
    }
    if (ht) {
        et = exp2f((vt - M) * c2);
        s += et;
    }
    #pragma unroll
    for (int o = 16; o; o >>= 1) s += __shfl_xor_sync(0xffffffffu, s, o);
    if (lane == 0) reds[wid] = s;
    __syncthreads();
    float Stot = 0.0f;
    #pragma unroll
    for (int w = 0; w < 8; ++w) Stot += reds[w];
    const float inv = 1.0f / Stot;

    if (h0) {
        __half2 a = __float22half2_rn(make_float2(e0.x * inv, e0.y * inv));
        __half2 b = __float22half2_rn(make_float2(e0.z * inv, e0.w * inv));
        uint2 o; o.x = *(unsigned*)&a; o.y = *(unsigned*)&b;
        ((uint2*)prow)[tid] = o;
    }
    if (h1) {
        __half2 a = __float22half2_rn(make_float2(e1.x * inv, e1.y * inv));
        __half2 b = __float22half2_rn(make_float2(e1.z * inv, e1.w * inv));
        uint2 o; o.x = *(unsigned*)&a; o.y = *(unsigned*)&b;
        ((uint2*)prow)[tid + 256] = o;
    }
    if (ht) prow[ti] = __float2half_rn(et * inv);

    const int zEnd = (qi & ~127) + 128;
    for (int j = L + tid; j < zEnd; j += 256) prow[j] = __float2half_rn(0.0f);
}

// ---------------------------------------------------------------------------
extern "C" void kernel_launch(void* const* d_in, const int* in_sizes, int n_in,
                              void* d_out, int out_size)
{
    (void)in_sizes; (void)n_in; (void)out_size;
    const float* x  = (const float*)d_in[0];
    const float* Wq = (const float*)d_in[1];
    const float* bq = (const float*)d_in[2];
    const float* Wk = (const float*)d_in[3];
    const float* bk = (const float*)d_in[4];
    const float* Wv = (const float*)d_in[5];
    const float* bv = (const float*)d_in[6];
    float* out = (float*)d_out;

    __half *xh, *wq, *wk, *wv, *qh, *kh, *vt, *p;
    float *s;
    cudaGetSymbolAddress((void**)&xh, g_xh);
    cudaGetSymbolAddress((void**)&wq, g_wq);
    cudaGetSymbolAddress((void**)&wk, g_wk);
    cudaGetSymbolAddress((void**)&wv, g_wv);
    cudaGetSymbolAddress((void**)&qh, g_qh);
    cudaGetSymbolAddress((void**)&kh, g_kh);
    cudaGetSymbolAddress((void**)&vt, g_vt);
    cudaGetSymbolAddress((void**)&p,  g_p);
    cudaGetSymbolAddress((void**)&s,  g_s);

    cudaFuncSetAttribute(mm_qkv,  cudaFuncAttributeMaxDynamicSharedMemorySize, SMEM_BYTES);
    cudaFuncSetAttribute(mm_h<1>, cudaFuncAttributeMaxDynamicSharedMemorySize, SMEM_BYTES);
    cudaFuncSetAttribute(mm_h<2>, cudaFuncAttributeMaxDynamicSharedMemorySize, SMEM_BYTES);

    dim3 blk(THREADS);

    // Fork/join plumbing (host objects only; kernel_launch runs on the
    // correctness call + capture call, so the small leak is bounded).
    cudaStream_t s2;
    cudaStreamCreateWithFlags(&s2, cudaStreamNonBlocking);
    cudaEvent_t eCvt, eV;
    cudaEventCreateWithFlags(&eCvt, cudaEventDisableTiming);
    cudaEventCreateWithFlags(&eV,   cudaEventDisableTiming);

    // Merged operand conversion (x + 3 weight matrices), main stream.
    const int nAll = NX8 + 3 * NW8;
    cvt_all<<<(nAll + 255) / 256, 256>>>(x, Wq, Wk, Wv, xh, wq, wk, wv);
    cudaEventRecord(eCvt, 0);

    // Fork: V projection (512 CTAs) on side stream — fills QK tail + scores head.
    cudaStreamWaitEvent(s2, eCvt, 0);
    dim3 gV(DM / BN, ROWS / BM, 1);
    mm_qkv<<<gV, blk, SMEM_BYTES, s2>>>(xh, wq, wk, wv, bq, bk, bv, qh, kh, vt, 2);
    cudaEventRecord(eV, s2);

    // Main stream: QK projections (1024 CTAs)
    dim3 gQK(DM / BN, ROWS / BM, 2);
    mm_qkv<<<gQK, blk, SMEM_BYTES>>>(xh, wq, wk, wv, bq, bk, bv, qh, kh, vt, 0);

    // Causal scores (fp32 out)
    dim3 gScores(SEQ / BN, SEQ / BM, BATCH);     // (16, 16, 4)
    mm_h<1><<<gScores, blk, SMEM_BYTES>>>(qh, kh, s);

    // Registerized row softmax (fp32 -> fp16 probs)
    softmax_kernel<<<ROWS, 256>>>(s, p);

    // Join: PV needs Vt complete.
    cudaStreamWaitEvent(0, eV, 0);

    // O = P Vt^T (fp32 out), longest CTAs first
    dim3 gPV(DM / BN, SEQ / BM, BATCH);          // (8, 16, 4)
    mm_h<2><<<gPV, blk, SMEM_BYTES>>>(p, vt, out);
}